// round 12
// baseline (speedup 1.0000x reference)
#include <cuda_runtime.h>
#include <math.h>
#include <stdint.h>

// FCOS post-process, GB300 (sm_103a), round 12.
// = round 11 + k_finish fast path: keys staged to SMEM once (verify fused),
//   warp-aggregated radix histograms (__match_any_sync), single-warp shfl
//   byte pick (12 barriers instead of 64, no hot-bin atomic serialization).

#define NIMG 8
#define NCLS 80
#define PP   15200
#define CPE  (NCLS*PP)        // 1216000
#define TOPK 1000
#define KPAD 1024
#define SEL  256              // early-stop NMS window
#define SRT  512              // sort width (SEL + tie slack)
#define CAP  262144
#define CAP2 2048
#define SKMAX 16384           // smem key staging capacity (128KB / 8B)
#define NSAMP 960
#define NITEM (NSAMP*10)
#define SBLK 38
#define TARGET_S 100
#define C0 (-2.9444389791664403f)   // logit(0.05)
typedef unsigned long long ull;
typedef unsigned int uint;

// ---------------- device scratch (module-load zeroed; self-cleaning) ---------
__device__ ull  g_cand[NIMG][CAP];                   // 16 MB
__device__ uint g_hist14[NIMG][4096];
__device__ uint g_candcnt[NIMG];
__device__ uint g_T[NIMG];
__device__ float g_xmin[NIMG][PP];
__device__ float g_box [NIMG][KPAD][4];
__device__ float g_obox[NIMG][KPAD][4];
__device__ float g_area[NIMG][KPAD];
__device__ float g_lab [NIMG][KPAD];
__device__ float g_sc  [NIMG][KPAD];
__device__ uint g_validbits[NIMG][32];

__device__ __forceinline__ float sig_exact(float v) {
    return 1.0f / (1.0f + expf(-v));
}
__device__ __forceinline__ float score_apx(float x, float eyp) {
    return __frcp_rn(__fmul_rn(__fadd_rn(1.0f, __expf(-x)), eyp));
}
__device__ __forceinline__ float4 f4max(float4 a, float4 b) {
    return make_float4(fmaxf(a.x, b.x), fmaxf(a.y, b.y),
                      fmaxf(a.z, b.z), fmaxf(a.w, b.w));
}

// Parallel radix-select over key high-32 bits in keys[0..M) (smem or global).
// On return smisc[0] = exact scorebits threshold for rank `rank`.
// blockDim = 1024. Warp-aggregated histogram + single-warp shfl byte pick.
__device__ void radix_select(const ull* __restrict__ keys, uint M, uint rank,
                             uint* shist, uint* smisc) {
    int t = threadIdx.x;
    int lane = t & 31;
    if (t == 0) { smisc[0] = 0u; smisc[1] = rank; }
    __syncthreads();
    for (int lvl = 3; lvl >= 0; lvl--) {
        if (t < 256) shist[t] = 0u;
        __syncthreads();
        uint pfx = smisc[0];
        for (uint base = 0; base < M; base += 1024) {   // padded: warp-converged
            uint idx = base + t;
            bool valid = idx < M;
            uint bits = valid ? (uint)(keys[idx] >> 32) : 0u;
            bool cond = valid && ((lvl == 3) || ((bits >> ((lvl + 1) * 8)) == pfx));
            uint bin = (bits >> (lvl * 8)) & 255u;
            uint tag = cond ? bin : (0x1000u + (uint)lane);   // unique sentinels
            uint grp = __match_any_sync(0xffffffffu, tag);
            if (cond) {
                int leader = __ffs(grp) - 1;
                if (lane == leader) atomicAdd(&shist[bin], (uint)__popc(grp));
            }
        }
        __syncthreads();
        if (t < 32) {                                 // warp 0: shfl byte pick
            uint s8[8]; uint ls = 0;
#pragma unroll
            for (int i = 0; i < 8; i++) { s8[i] = shist[t * 8 + i]; ls += s8[i]; }
            uint v = ls;                              // inclusive suffix over lanes
#pragma unroll
            for (int off = 1; off < 32; off <<= 1) {
                uint u = __shfl_down_sync(0xffffffffu, v, off);
                if (lane + off < 32) v += u;
            }
            uint rr = smisc[1];
            uint cum_start = v - ls;                  // sum of strictly-higher bins
            if (v >= rr && cum_start < rr) {          // crossing in this lane
                uint cum = cum_start;
                for (int i = 7; i >= 0; i--) {
                    cum += s8[i];
                    if (cum >= rr) {
                        smisc[1] = rr - (cum - s8[i]);
                        smisc[0] = (smisc[0] << 8) | (uint)(t * 8 + i);
                        break;
                    }
                }
            }
        }
        __syncthreads();
    }
}

// ---------------- K1: sampled hist via SMEM, sparse merge --------------------
__global__ __launch_bounds__(256) void k_hist(const float* __restrict__ cls,
                                              const float* __restrict__ ctr) {
    __shared__ uint sh[4096];
    int n = blockIdx.y;
    int t = threadIdx.x;
    for (int q = t; q < 4096; q += 256) sh[q] = 0u;
    __syncthreads();
    int item = blockIdx.x * 256 + t;
    if (item < NITEM) {
        int k  = item % NSAMP;
        int cb = item / NSAMP;
        int p = (k >> 4) * 253 + (k & 15);           // 60 runs of 16 points
        float eyp = __fadd_rn(1.0f, __expf(-ctr[(size_t)n * PP + p]));
        const float* base = cls + (size_t)n * CPE + p + (size_t)cb * 8 * PP;
        float xs[8];
#pragma unroll
        for (int i = 0; i < 8; i++) xs[i] = base[(size_t)i * PP];
#pragma unroll
        for (int i = 0; i < 8; i++) {
            if (xs[i] > C0) {
                uint b14 = __float_as_uint(score_apx(xs[i], eyp)) >> 18;
                if (b14 > 4095u) b14 = 4095u;
                if (b14) atomicAdd(&sh[b14], 1u);
            }
        }
    }
    __syncthreads();
    for (int q = t; q < 4096; q += 256) {
        uint v = sh[q];
        if (v) atomicAdd(&g_hist14[n][q], v);        // sparse: few hundred/block
    }
}

// ---------------- K2: per-block t14 + xmin slice (grid 60 x NIMG) ------------
__global__ __launch_bounds__(256) void k_prep(const float* __restrict__ ctr) {
    __shared__ uint ss[256];
    __shared__ float s_edge;
    int n = blockIdx.y;
    int t = threadIdx.x;
    uint loc[16]; uint s = 0;
#pragma unroll
    for (int i = 0; i < 16; i++) { loc[i] = g_hist14[n][t * 16 + i]; s += loc[i]; }
    ss[t] = s;
    __syncthreads();
    for (int off = 1; off < 256; off <<= 1) {        // suffix scan
        uint v = (t + off < 256) ? ss[t + off] : 0u;
        __syncthreads();
        ss[t] += v;
        __syncthreads();
    }
    uint mine = ss[t];
    uint above = (t + 1 < 256) ? ss[t + 1] : 0u;
    if (mine >= TARGET_S && above < TARGET_S) {      // unique crossing chunk
        uint cum = above, T = 1;
        for (int i = 15; i >= 0; i--) {
            cum += loc[i];
            if (cum >= TARGET_S) { T = (uint)(t * 16 + i); break; }
        }
        if (T < 1) T = 1;
        uint gate = (T > 2) ? T - 1 : 1u;
        g_T[n] = T;                                  // identical across blocks
        s_edge = __uint_as_float(gate << 18);
    }
    if (t == 0 && ss[0] < TARGET_S) {                // degenerate: keep all
        g_T[n] = 1;
        s_edge = __uint_as_float(1u << 18);
    }
    __syncthreads();
    float edge = s_edge;
    int p = blockIdx.x * 256 + t;
    if (p < PP) {
        float eyp = __fadd_rn(1.0f, __expf(-ctr[(size_t)n * PP + p]));
        float K = __fdividef(1.0f, __fmul_rn(edge, eyp)) - 1.0f;
        float xm = (K > 0.0f) ? (-__logf(K) - 0.002f) : 3.0e38f;
        g_xmin[n][p] = fmaxf(xm, C0);
    }
}

// ---------------- K3: max-gated full scan, 4 classes/thread ------------------
__global__ __launch_bounds__(256) void k_compact(const float* __restrict__ cls,
                                                 const float* __restrict__ ctr) {
    int n = blockIdx.z;
    int q = blockIdx.x * 256 + threadIdx.x;
    if (q >= PP / 4) return;
    int pb = q * 4;
    float4 xm4 = *(const float4*)&g_xmin[n][pb];
    float xm[4] = {xm4.x, xm4.y, xm4.z, xm4.w};
    int c0 = blockIdx.y * 4;
    const float* base = cls + (size_t)n * CPE + pb;
    float4 xv[4];
#pragma unroll
    for (int i = 0; i < 4; i++)
        xv[i] = *(const float4*)(base + (size_t)(c0 + i) * PP);
    float4 m4 = f4max(f4max(xv[0], xv[1]), f4max(xv[2], xv[3]));
    float mj[4] = {m4.x, m4.y, m4.z, m4.w};
#pragma unroll
    for (int j = 0; j < 4; j++) {
        if (mj[j] >= xm[j]) {                        // rare: some class passes
#pragma unroll
            for (int i = 0; i < 4; i++) {
                float x = (j == 0) ? xv[i].x : (j == 1) ? xv[i].y
                        : (j == 2) ? xv[i].z : xv[i].w;
                if (x >= xm[j]) {
                    float s = sig_exact(x);
                    if (s > 0.05f) {                 // exact candidacy
                        float y = ctr[(size_t)n * PP + pb + j];
                        float score = __fmul_rn(s, sig_exact(y));
                        uint sb = __float_as_uint(score);
                        uint idx = (uint)((pb + j) * NCLS + (c0 + i));
                        ull key = ((ull)sb << 32) | (ull)(0xFFFFFFFFu - idx);
                        uint pos = atomicAdd(&g_candcnt[n], 1u);
                        if (pos < CAP) g_cand[n][pos] = key;
                    }
                }
            }
        }
    }
}

// ---------------- decode helper ----------------------------------------------
__device__ __forceinline__ void decode_one(int n, ull key,
        const float* loc, const float* reg, const float* info,
        float4* box4, float4* ob4, float* area, float* lab, float* sc, bool* valid) {
    float x1 = 0, y1 = 0, x2 = 0, y2 = 0, labf = 0, score = 0;
    float ox1 = 0, oy1 = 0, ox2 = 0, oy2 = 0, ar = 0;
    bool vld = false;
    uint sb = (uint)(key >> 32);
    if (sb) {
        score = __uint_as_float(sb);
        uint i = 0xFFFFFFFFu - (uint)(key & 0xFFFFFFFFull);
        int p = (int)(i / NCLS);
        int c = (int)(i - (uint)(p * NCLS));
        labf = (float)(c + 1);
        float lx = loc[2 * p], ly = loc[2 * p + 1];
        float rl = reg[((size_t)(n * 4 + 0)) * PP + p];
        float rt = reg[((size_t)(n * 4 + 1)) * PP + p];
        float rr = reg[((size_t)(n * 4 + 2)) * PP + p];
        float rb = reg[((size_t)(n * 4 + 3)) * PP + p];
        float hm1 = __fsub_rn(info[2 * n + 0], 1.0f);
        float wm1 = __fsub_rn(info[2 * n + 1], 1.0f);
        x1 = fminf(fmaxf(__fsub_rn(lx, rl), 0.0f), wm1);
        y1 = fminf(fmaxf(__fsub_rn(ly, rt), 0.0f), hm1);
        x2 = fminf(fmaxf(__fadd_rn(lx, rr), 0.0f), wm1);
        y2 = fminf(fmaxf(__fadd_rn(ly, rb), 0.0f), hm1);
        vld = (score > 0.0f) &&
              (__fsub_rn(x2, x1) >= 0.0f) && (__fsub_rn(y2, y1) >= 0.0f);
        float off = __fmul_rn(labf, 1.0e5f);
        ox1 = __fadd_rn(x1, off); oy1 = __fadd_rn(y1, off);
        ox2 = __fadd_rn(x2, off); oy2 = __fadd_rn(y2, off);
        ar = __fmul_rn(fmaxf(__fsub_rn(ox2, ox1), 0.0f),
                       fmaxf(__fsub_rn(oy2, oy1), 0.0f));
    }
    *box4 = make_float4(x1, y1, x2, y2);
    *ob4  = make_float4(ox1, oy1, ox2, oy2);
    *area = ar; *lab = labf; *sc = score; *valid = vld;
}

__device__ __forceinline__ bool iou_sup(float4 bi, float ai, float4 bj, float aj) {
    float wv = fmaxf(__fsub_rn(fminf(bi.z, bj.z), fmaxf(bi.x, bj.x)), 0.0f);
    float hv = fmaxf(__fsub_rn(fminf(bi.w, bj.w), fmaxf(bi.y, bj.y)), 0.0f);
    float inter = __fmul_rn(wv, hv);
    float denom = __fadd_rn(__fsub_rn(__fadd_rn(ai, aj), inter), 1e-9f);
    return inter > __fmul_rn(0.6f, denom);           // iou > 0.6
}

// ---------------- full refine (slow path only; reads g_cand) -----------------
__device__ void refine_core(int n, uint M,
                            const float* __restrict__ loc,
                            const float* __restrict__ reg,
                            const float* __restrict__ info,
                            ull* slist, uint* shist, uint* smisc) {
    int t = threadIdx.x;
    if (M <= CAP2) {
        for (int q = t; q < CAP2; q += 1024)
            slist[q] = (q < (int)M) ? g_cand[n][q] : 0ull;
        __syncthreads();
    } else {
        radix_select(&g_cand[n][0], M, TOPK, shist, smisc);
        uint sstar = smisc[0];
        if (t == 0) smisc[2] = 0u;
        for (int q = t; q < CAP2; q += 1024) slist[q] = 0ull;
        __syncthreads();
        for (uint idx = t; idx < M; idx += 1024) {
            ull key = g_cand[n][idx];
            if ((uint)(key >> 32) >= sstar) {
                uint pos = atomicAdd(&smisc[2], 1u);
                if (pos < CAP2) slist[pos] = key;
            }
        }
        __syncthreads();
    }
    for (int k2 = 2; k2 <= CAP2; k2 <<= 1) {
        for (int s2 = k2 >> 1; s2 >= 1; s2 >>= 1) {
            int i = ((t & ~(s2 - 1)) << 1) | (t & (s2 - 1));
            int l = i | s2;
            ull a = slist[i], b = slist[l];
            bool dir = ((i & k2) == 0);
            if ((a < b) == dir) { slist[i] = b; slist[l] = a; }
            __syncthreads();
        }
    }
    bool vld = false;
    float4 bx, ob; float ar, lb, sc;
    if (t < TOPK) {
        decode_one(n, slist[t], loc, reg, info, &bx, &ob, &ar, &lb, &sc, &vld);
    } else {
        bx = make_float4(0, 0, 0, 0); ob = bx; ar = 0; lb = 0; sc = 0;
    }
    *(float4*)&g_box[n][t][0] = bx;
    *(float4*)&g_obox[n][t][0] = ob;
    g_area[n][t] = ar; g_lab[n][t] = lb; g_sc[n][t] = sc;
    uint bal = __ballot_sync(0xffffffffu, vld);
    if ((t & 31) == 0) g_validbits[n][t >> 5] = bal;
}

// ---------------- K4: finish (fast top-256 path + inline full fallback) ------
__global__ __launch_bounds__(1024, 1) void k_finish(const float* __restrict__ cls,
                                                    const float* __restrict__ ctr,
                                                    const float* __restrict__ loc,
                                                    const float* __restrict__ reg,
                                                    const float* __restrict__ info,
                                                    float* __restrict__ out) {
    extern __shared__ uint smaskd[];                 // 128 KB: key staging, then
                                                     // full-path mask (slow path)
    __shared__ ull slist[CAP2];                      // 16 KB (fast uses [0,SRT))
    __shared__ uint shist[256];
    __shared__ uint smisc[8];
    __shared__ float4 sbox[SEL], sob[SEL];
    __shared__ float sar[SEL], slb[SEL], ssc[SEL];
    __shared__ uint svalid[8];
    __shared__ uint smask[SEL * 8];                  // 8 KB
    __shared__ int s_path;                           // 0 fast-ok, 1 rebuild, 2 full-nms
    __shared__ float4 sobF[KPAD];
    __shared__ float sarF[KPAD], slbF[KPAD];
    int n = blockIdx.x;
    int t = threadIdx.x;
    int lane = t & 31;
    ull* skeys = (ull*)smaskd;                       // staging: up to SKMAX keys
    if (t < 600) out[(size_t)n * 600 + t] = 0.0f;
    for (int q = t; q < 4096; q += 1024) g_hist14[n][q] = 0u;   // reset for next call
    uint attempted = g_candcnt[n];
    uint M = attempted > CAP ? CAP : attempted;
    bool staged = (M <= SKMAX);
    if (t == 0) { smisc[3] = 0u; s_path = 0; }
    __syncthreads();
    // stage keys to SMEM (if they fit) + fused completeness count
    {
        uint Vb = g_T[n] << 18;
        uint local = 0;
        for (uint idx = t; idx < M; idx += 1024) {
            ull key = g_cand[n][idx];
            if (staged) skeys[idx] = key;
            if ((uint)(key >> 32) >= Vb) local++;
        }
        if (local) atomicAdd(&smisc[3], local);
    }
    __syncthreads();
    if (smisc[3] < TOPK || attempted > CAP) {
        if (t == 0) s_path = 1;
    }
    __syncthreads();
    const ull* keys = staged ? (const ull*)skeys : &g_cand[n][0];
    if (s_path == 0) {
        // ---- fast path: radix select exact rank-SEL threshold ----
        radix_select(keys, M, SEL, shist, smisc);
        uint sstar = smisc[0];
        if (t == 0) smisc[2] = 0u;
        if (t < SRT) slist[t] = 0ull;
        __syncthreads();
        for (uint idx = t; idx < M; idx += 1024) {
            ull key = keys[idx];
            if ((uint)(key >> 32) >= sstar) {
                uint pos = atomicAdd(&smisc[2], 1u);
                if (pos < SRT) slist[pos] = key;
            }
        }
        __syncthreads();
        if (smisc[2] > SRT) {                        // absurd tie explosion
            if (t == 0) s_path = 2;
        }
        __syncthreads();
        if (s_path == 0) {
            for (int k2 = 2; k2 <= SRT; k2 <<= 1) {
                for (int s2 = k2 >> 1; s2 >= 1; s2 >>= 1) {
                    if (t < SRT / 2) {
                        int i = ((t & ~(s2 - 1)) << 1) | (t & (s2 - 1));
                        int l = i | s2;
                        ull a = slist[i], b = slist[l];
                        bool dir = ((i & k2) == 0);
                        if ((a < b) == dir) { slist[i] = b; slist[l] = a; }
                    }
                    __syncthreads();
                }
            }
            if (t < SEL) {
                bool vld;
                decode_one(n, slist[t], loc, reg, info,
                           &sbox[t], &sob[t], &sar[t], &slb[t], &ssc[t], &vld);
                uint bal = __ballot_sync(0xffffffffu, vld);
                if ((t & 31) == 0) svalid[t >> 5] = bal;
            }
            __syncthreads();
            {
                int warp = t >> 5;
#pragma unroll
                for (int r = 0; r < 8; r++) {
                    int i = warp * 8 + r;
                    float4 bi = sob[i];
                    float ai = sar[i];
                    float li = slb[i];
#pragma unroll
                    for (int wd = 0; wd < 8; wd++) {
                        int j = wd * 32 + lane;
                        bool sup = false;
                        if (j > i && slb[j] == li)
                            sup = iou_sup(bi, ai, sob[j], sar[j]);
                        uint bits = __ballot_sync(0xffffffffu, sup);
                        if (lane == 0) smask[i * 8 + wd] = bits;
                    }
                }
            }
            __syncthreads();
            if (t < 32) {
                uint validw = (lane < 8) ? svalid[lane] : 0u;
                uint removew = 0u;
                for (int g = 0; g < 8; g++) {
                    uint cur_sup = __shfl_sync(0xffffffffu, removew, g);
                    uint cur_val = __shfl_sync(0xffffffffu, validw, g);
                    uint rowv[32], diag[32];
#pragma unroll
                    for (int b = 0; b < 32; b++) {
                        rowv[b] = (lane < 8) ? smask[(g * 32 + b) * 8 + lane] : 0u;
                        diag[b] = smask[(g * 32 + b) * 8 + g];
                    }
#pragma unroll
                    for (int b = 0; b < 32; b++) {
                        bool alive = ((cur_val >> b) & 1u) && !((cur_sup >> b) & 1u);
                        if (alive) { removew |= rowv[b]; cur_sup |= diag[b]; }
                    }
                }
                uint keepw = validw & ~removew;
                int kv = __popc(keepw);
                int tot = kv;
#pragma unroll
                for (int o = 1; o < 32; o <<= 1)     // full-warp: uniform tot
                    tot += __shfl_xor_sync(0xffffffffu, tot, o);
                if (tot >= 100) {
                    int inc = kv;
                    for (int o = 1; o < 32; o <<= 1) {
                        int v = __shfl_up_sync(0xffffffffu, inc, o);
                        if (lane >= o) inc += v;
                    }
                    int basei = inc - kv;
                    uint m = keepw;
                    while (m) {
                        int b = __ffs(m) - 1;
                        m &= m - 1;
                        int rank = basei + __popc(keepw & ((1u << b) - 1u));
                        if (rank < 100) {
                            int i = lane * 32 + b;
                            float* o6 = out + ((size_t)n * 100 + rank) * 6;
                            float4 bx = sbox[i];
                            o6[0] = bx.x; o6[1] = bx.y; o6[2] = bx.z; o6[3] = bx.w;
                            o6[4] = slb[i]; o6[5] = ssc[i];
                        }
                    }
                } else if (lane == 0) {
                    s_path = 2;                      // need full-width NMS
                }
            }
            __syncthreads();
        }
    }
    if (s_path == 0) {
        if (t == 0) g_candcnt[n] = 0u;
        return;                                      // fast path done
    }
    // ================= slow path (guarded; never in practice) =================
    if (s_path == 1) {                               // exact candidate rebuild
        if (t < 256) shist[t] = 0u;
        if (t == 0) g_candcnt[n] = 0u;
        __syncthreads();
        const float* clsn = cls + (size_t)n * CPE;
        const float* ctrn = ctr + (size_t)n * PP;
        for (int j = t; j < CPE; j += 1024) {
            int p = j % PP;
            float s = sig_exact(clsn[j]);
            if (s > 0.05f) {
                uint b = __float_as_uint(__fmul_rn(s, sig_exact(ctrn[p]))) >> 24;
                if (b) atomicAdd(&shist[b], 1u);
            }
        }
        __syncthreads();
        if (t == 0) {
            uint cum = 0, b1 = 1;
            for (int b = 255; b >= 1; b--) {
                cum += shist[b];
                if (cum >= TOPK) { b1 = (uint)b; break; }
            }
            smisc[4] = b1;
        }
        __syncthreads();
        uint b1 = smisc[4];
        for (int j = t; j < CPE; j += 1024) {
            int p = j % PP;
            float s = sig_exact(clsn[j]);
            if (s > 0.05f) {
                float score = __fmul_rn(s, sig_exact(ctrn[p]));
                uint sb = __float_as_uint(score);
                if ((sb >> 24) >= b1) {
                    int c = j / PP;
                    uint i = (uint)(p * NCLS + c);
                    ull key = ((ull)sb << 32) | (ull)(0xFFFFFFFFu - i);
                    uint pos = atomicAdd(&g_candcnt[n], 1u);
                    if (pos < CAP) g_cand[n][pos] = key;
                }
            }
        }
        __syncthreads();
        attempted = g_candcnt[n];
        M = attempted > CAP ? CAP : attempted;
    }
    refine_core(n, M, loc, reg, info, slist, shist, smisc);
    __syncthreads();
    if (t < 600) out[(size_t)n * 600 + t] = 0.0f;    // re-zero (fast may have run)
    sobF[t] = *(float4*)&g_obox[n][t][0];
    sarF[t] = g_area[n][t];
    slbF[t] = g_lab[n][t];
    __syncthreads();
    int warp = t >> 5;
    for (int r = 0; r < 32; r++) {
        int i = r * 32 + warp;
        float4 bi = sobF[i];
        float ai = sarF[i];
        float li = slbF[i];
        uint myword = 0u;
        for (int w = r; w < 32; w++) {
            int j = w * 32 + lane;
            bool sup = false;
            if (j > i && slbF[j] == li)
                sup = iou_sup(bi, ai, sobF[j], sarF[j]);
            uint bits = __ballot_sync(0xffffffffu, sup);
            if (lane == w) myword = bits;
        }
        smaskd[i * 32 + lane] = (lane >= r) ? myword : 0u;
    }
    __syncthreads();
    if (t < 32) {
        uint validw = g_validbits[n][lane];
        uint removew = 0u;
        for (int g = 0; g < 32; g++) {
            uint cur_sup = __shfl_sync(0xffffffffu, removew, g);
            uint cur_val = __shfl_sync(0xffffffffu, validw, g);
            uint rowv[32], diag[32];
#pragma unroll
            for (int b = 0; b < 32; b++) {
                rowv[b] = smaskd[(g * 32 + b) * 32 + lane];
                diag[b] = smaskd[(g * 32 + b) * 32 + g];
            }
#pragma unroll
            for (int b = 0; b < 32; b++) {
                bool alive = ((cur_val >> b) & 1u) && !((cur_sup >> b) & 1u);
                if (alive) { removew |= rowv[b]; cur_sup |= diag[b]; }
            }
        }
        uint keepw = validw & ~removew;
        int cnt = __popc(keepw);
        int inc = cnt;
        for (int o = 1; o < 32; o <<= 1) {
            int v = __shfl_up_sync(0xffffffffu, inc, o);
            if (lane >= o) inc += v;
        }
        int basei = inc - cnt;
        uint m = keepw;
        while (m) {
            int b = __ffs(m) - 1;
            m &= m - 1;
            int rank = basei + __popc(keepw & ((1u << b) - 1u));
            if (rank < 100) {
                int i = lane * 32 + b;
                float* o6 = out + ((size_t)n * 100 + rank) * 6;
                o6[0] = g_box[n][i][0]; o6[1] = g_box[n][i][1];
                o6[2] = g_box[n][i][2]; o6[3] = g_box[n][i][3];
                o6[4] = g_lab[n][i];    o6[5] = g_sc[n][i];
            }
        }
    }
    __syncthreads();
    if (t == 0) g_candcnt[n] = 0u;
}

// ---------------- launch -----------------------------------------------------
extern "C" void kernel_launch(void* const* d_in, const int* in_sizes, int n_in,
                              void* d_out, int out_size) {
    const float* loc  = (const float*)d_in[0];
    const float* cls  = (const float*)d_in[1];
    const float* reg  = (const float*)d_in[2];
    const float* ctr  = (const float*)d_in[3];
    const float* info = (const float*)d_in[4];
    float* out = (float*)d_out;
    (void)in_sizes; (void)n_in; (void)out_size;

    cudaFuncSetAttribute(k_finish, cudaFuncAttributeMaxDynamicSharedMemorySize,
                         KPAD * 32 * 4);

    k_hist<<<dim3(SBLK, NIMG), 256>>>(cls, ctr);
    k_prep<<<dim3(60, NIMG), 256>>>(ctr);
    k_compact<<<dim3(15, 20, NIMG), 256>>>(cls, ctr);
    k_finish<<<NIMG, 1024, KPAD * 32 * 4>>>(cls, ctr, loc, reg, info, out);
}

// round 13
// speedup vs baseline: 1.1722x; 1.1722x over previous
#include <cuda_runtime.h>
#include <math.h>
#include <stdint.h>

// FCOS post-process, GB300 (sm_103a), round 13.
// = round 11, with the k_finish fast path reworked:
//   fused verify + exact 4096-bin hist -> suffix-scan bin threshold (W in
//   [SEL,SRT] verified at runtime) -> compact -> rank-by-counting sort
//   (no radix passes, no bitonic barriers). Slow path = R11, unchanged.

#define NIMG 8
#define NCLS 80
#define PP   15200
#define CPE  (NCLS*PP)        // 1216000
#define TOPK 1000
#define KPAD 1024
#define SEL  256              // early-stop NMS window
#define SRT  512              // selection width cap (SEL + slack)
#define CAP  262144
#define CAP2 2048
#define NSAMP 960
#define NITEM (NSAMP*10)
#define SBLK 38
#define TARGET_S 100
#define C0 (-2.9444389791664403f)   // logit(0.05)
typedef unsigned long long ull;
typedef unsigned int uint;

// ---------------- device scratch (module-load zeroed; self-cleaning) ---------
__device__ ull  g_cand[NIMG][CAP];                   // 16 MB
__device__ uint g_hist14[NIMG][4096];
__device__ uint g_candcnt[NIMG];
__device__ uint g_T[NIMG];
__device__ float g_xmin[NIMG][PP];
__device__ float g_box [NIMG][KPAD][4];
__device__ float g_obox[NIMG][KPAD][4];
__device__ float g_area[NIMG][KPAD];
__device__ float g_lab [NIMG][KPAD];
__device__ float g_sc  [NIMG][KPAD];
__device__ uint g_validbits[NIMG][32];

__device__ __forceinline__ float sig_exact(float v) {
    return 1.0f / (1.0f + expf(-v));
}
__device__ __forceinline__ float score_apx(float x, float eyp) {
    return __frcp_rn(__fmul_rn(__fadd_rn(1.0f, __expf(-x)), eyp));
}
__device__ __forceinline__ float4 f4max(float4 a, float4 b) {
    return make_float4(fmaxf(a.x, b.x), fmaxf(a.y, b.y),
                      fmaxf(a.z, b.z), fmaxf(a.w, b.w));
}

// R11 radix-select (slow path only). smisc[0] = exact threshold for `rank`.
__device__ void radix_select(int n, uint M, uint rank, uint* shist, uint* smisc) {
    int t = threadIdx.x;
    int bdim = blockDim.x;
    if (t == 0) { smisc[0] = 0u; smisc[1] = rank; }
    __syncthreads();
    for (int lvl = 3; lvl >= 0; lvl--) {
        if (t < 256) shist[t] = 0u;
        __syncthreads();
        uint pfx = smisc[0];
        for (uint idx = t; idx < M; idx += bdim) {
            uint bits = (uint)(g_cand[n][idx] >> 32);
            bool cond = (lvl == 3) || ((bits >> ((lvl + 1) * 8)) == pfx);
            if (cond) atomicAdd(&shist[(bits >> (lvl * 8)) & 255u], 1u);
        }
        __syncthreads();
        for (int off = 1; off < 256; off <<= 1) {
            uint v = 0;
            if (t < 256 && t + off < 256) v = shist[t + off];
            __syncthreads();
            if (t < 256) shist[t] += v;
            __syncthreads();
        }
        if (t < 256) {
            uint rr = smisc[1];
            uint mine = shist[t];
            uint above = (t < 255) ? shist[t + 1] : 0u;
            if (mine >= rr && above < rr) {
                smisc[1] = rr - above;
                smisc[0] = (smisc[0] << 8) | (uint)t;
            }
        }
        __syncthreads();
    }
}

// ---------------- K1: sampled hist via SMEM, sparse merge --------------------
__global__ __launch_bounds__(256) void k_hist(const float* __restrict__ cls,
                                              const float* __restrict__ ctr) {
    __shared__ uint sh[4096];
    int n = blockIdx.y;
    int t = threadIdx.x;
    for (int q = t; q < 4096; q += 256) sh[q] = 0u;
    __syncthreads();
    int item = blockIdx.x * 256 + t;
    if (item < NITEM) {
        int k  = item % NSAMP;
        int cb = item / NSAMP;
        int p = (k >> 4) * 253 + (k & 15);           // 60 runs of 16 points
        float eyp = __fadd_rn(1.0f, __expf(-ctr[(size_t)n * PP + p]));
        const float* base = cls + (size_t)n * CPE + p + (size_t)cb * 8 * PP;
        float xs[8];
#pragma unroll
        for (int i = 0; i < 8; i++) xs[i] = base[(size_t)i * PP];
#pragma unroll
        for (int i = 0; i < 8; i++) {
            if (xs[i] > C0) {
                uint b14 = __float_as_uint(score_apx(xs[i], eyp)) >> 18;
                if (b14 > 4095u) b14 = 4095u;
                if (b14) atomicAdd(&sh[b14], 1u);
            }
        }
    }
    __syncthreads();
    for (int q = t; q < 4096; q += 256) {
        uint v = sh[q];
        if (v) atomicAdd(&g_hist14[n][q], v);        // sparse: few hundred/block
    }
}

// ---------------- K2: per-block t14 + xmin slice (grid 60 x NIMG) ------------
__global__ __launch_bounds__(256) void k_prep(const float* __restrict__ ctr) {
    __shared__ uint ss[256];
    __shared__ float s_edge;
    int n = blockIdx.y;
    int t = threadIdx.x;
    uint loc[16]; uint s = 0;
#pragma unroll
    for (int i = 0; i < 16; i++) { loc[i] = g_hist14[n][t * 16 + i]; s += loc[i]; }
    ss[t] = s;
    __syncthreads();
    for (int off = 1; off < 256; off <<= 1) {        // suffix scan
        uint v = (t + off < 256) ? ss[t + off] : 0u;
        __syncthreads();
        ss[t] += v;
        __syncthreads();
    }
    uint mine = ss[t];
    uint above = (t + 1 < 256) ? ss[t + 1] : 0u;
    if (mine >= TARGET_S && above < TARGET_S) {      // unique crossing chunk
        uint cum = above, T = 1;
        for (int i = 15; i >= 0; i--) {
            cum += loc[i];
            if (cum >= TARGET_S) { T = (uint)(t * 16 + i); break; }
        }
        if (T < 1) T = 1;
        uint gate = (T > 2) ? T - 1 : 1u;
        g_T[n] = T;                                  // identical across blocks
        s_edge = __uint_as_float(gate << 18);
    }
    if (t == 0 && ss[0] < TARGET_S) {                // degenerate: keep all
        g_T[n] = 1;
        s_edge = __uint_as_float(1u << 18);
    }
    __syncthreads();
    float edge = s_edge;
    int p = blockIdx.x * 256 + t;
    if (p < PP) {
        float eyp = __fadd_rn(1.0f, __expf(-ctr[(size_t)n * PP + p]));
        float K = __fdividef(1.0f, __fmul_rn(edge, eyp)) - 1.0f;
        float xm = (K > 0.0f) ? (-__logf(K) - 0.002f) : 3.0e38f;
        g_xmin[n][p] = fmaxf(xm, C0);
    }
}

// ---------------- K3: max-gated full scan, 4 classes/thread ------------------
__global__ __launch_bounds__(256) void k_compact(const float* __restrict__ cls,
                                                 const float* __restrict__ ctr) {
    int n = blockIdx.z;
    int q = blockIdx.x * 256 + threadIdx.x;
    if (q >= PP / 4) return;
    int pb = q * 4;
    float4 xm4 = *(const float4*)&g_xmin[n][pb];
    float xm[4] = {xm4.x, xm4.y, xm4.z, xm4.w};
    int c0 = blockIdx.y * 4;
    const float* base = cls + (size_t)n * CPE + pb;
    float4 xv[4];
#pragma unroll
    for (int i = 0; i < 4; i++)
        xv[i] = *(const float4*)(base + (size_t)(c0 + i) * PP);
    float4 m4 = f4max(f4max(xv[0], xv[1]), f4max(xv[2], xv[3]));
    float mj[4] = {m4.x, m4.y, m4.z, m4.w};
#pragma unroll
    for (int j = 0; j < 4; j++) {
        if (mj[j] >= xm[j]) {                        // rare: some class passes
#pragma unroll
            for (int i = 0; i < 4; i++) {
                float x = (j == 0) ? xv[i].x : (j == 1) ? xv[i].y
                        : (j == 2) ? xv[i].z : xv[i].w;
                if (x >= xm[j]) {
                    float s = sig_exact(x);
                    if (s > 0.05f) {                 // exact candidacy
                        float y = ctr[(size_t)n * PP + pb + j];
                        float score = __fmul_rn(s, sig_exact(y));
                        uint sb = __float_as_uint(score);
                        uint idx = (uint)((pb + j) * NCLS + (c0 + i));
                        ull key = ((ull)sb << 32) | (ull)(0xFFFFFFFFu - idx);
                        uint pos = atomicAdd(&g_candcnt[n], 1u);
                        if (pos < CAP) g_cand[n][pos] = key;
                    }
                }
            }
        }
    }
}

// ---------------- decode helper ----------------------------------------------
__device__ __forceinline__ void decode_one(int n, ull key,
        const float* loc, const float* reg, const float* info,
        float4* box4, float4* ob4, float* area, float* lab, float* sc, bool* valid) {
    float x1 = 0, y1 = 0, x2 = 0, y2 = 0, labf = 0, score = 0;
    float ox1 = 0, oy1 = 0, ox2 = 0, oy2 = 0, ar = 0;
    bool vld = false;
    uint sb = (uint)(key >> 32);
    if (sb) {
        score = __uint_as_float(sb);
        uint i = 0xFFFFFFFFu - (uint)(key & 0xFFFFFFFFull);
        int p = (int)(i / NCLS);
        int c = (int)(i - (uint)(p * NCLS));
        labf = (float)(c + 1);
        float lx = loc[2 * p], ly = loc[2 * p + 1];
        float rl = reg[((size_t)(n * 4 + 0)) * PP + p];
        float rt = reg[((size_t)(n * 4 + 1)) * PP + p];
        float rr = reg[((size_t)(n * 4 + 2)) * PP + p];
        float rb = reg[((size_t)(n * 4 + 3)) * PP + p];
        float hm1 = __fsub_rn(info[2 * n + 0], 1.0f);
        float wm1 = __fsub_rn(info[2 * n + 1], 1.0f);
        x1 = fminf(fmaxf(__fsub_rn(lx, rl), 0.0f), wm1);
        y1 = fminf(fmaxf(__fsub_rn(ly, rt), 0.0f), hm1);
        x2 = fminf(fmaxf(__fadd_rn(lx, rr), 0.0f), wm1);
        y2 = fminf(fmaxf(__fadd_rn(ly, rb), 0.0f), hm1);
        vld = (score > 0.0f) &&
              (__fsub_rn(x2, x1) >= 0.0f) && (__fsub_rn(y2, y1) >= 0.0f);
        float off = __fmul_rn(labf, 1.0e5f);
        ox1 = __fadd_rn(x1, off); oy1 = __fadd_rn(y1, off);
        ox2 = __fadd_rn(x2, off); oy2 = __fadd_rn(y2, off);
        ar = __fmul_rn(fmaxf(__fsub_rn(ox2, ox1), 0.0f),
                       fmaxf(__fsub_rn(oy2, oy1), 0.0f));
    }
    *box4 = make_float4(x1, y1, x2, y2);
    *ob4  = make_float4(ox1, oy1, ox2, oy2);
    *area = ar; *lab = labf; *sc = score; *valid = vld;
}

__device__ __forceinline__ bool iou_sup(float4 bi, float ai, float4 bj, float aj) {
    float wv = fmaxf(__fsub_rn(fminf(bi.z, bj.z), fmaxf(bi.x, bj.x)), 0.0f);
    float hv = fmaxf(__fsub_rn(fminf(bi.w, bj.w), fmaxf(bi.y, bj.y)), 0.0f);
    float inter = __fmul_rn(wv, hv);
    float denom = __fadd_rn(__fsub_rn(__fadd_rn(ai, aj), inter), 1e-9f);
    return inter > __fmul_rn(0.6f, denom);           // iou > 0.6
}

// ---------------- full refine (slow path only; R11 proven) -------------------
__device__ void refine_core(int n, uint M,
                            const float* __restrict__ loc,
                            const float* __restrict__ reg,
                            const float* __restrict__ info,
                            ull* slist, uint* shist, uint* smisc) {
    int t = threadIdx.x;
    if (M <= CAP2) {
        for (int q = t; q < CAP2; q += 1024)
            slist[q] = (q < (int)M) ? g_cand[n][q] : 0ull;
        __syncthreads();
    } else {
        radix_select(n, M, TOPK, shist, smisc);
        uint sstar = smisc[0];
        if (t == 0) smisc[2] = 0u;
        for (int q = t; q < CAP2; q += 1024) slist[q] = 0ull;
        __syncthreads();
        for (uint idx = t; idx < M; idx += 1024) {
            ull key = g_cand[n][idx];
            if ((uint)(key >> 32) >= sstar) {
                uint pos = atomicAdd(&smisc[2], 1u);
                if (pos < CAP2) slist[pos] = key;
            }
        }
        __syncthreads();
    }
    for (int k2 = 2; k2 <= CAP2; k2 <<= 1) {
        for (int s2 = k2 >> 1; s2 >= 1; s2 >>= 1) {
            int i = ((t & ~(s2 - 1)) << 1) | (t & (s2 - 1));
            int l = i | s2;
            ull a = slist[i], b = slist[l];
            bool dir = ((i & k2) == 0);
            if ((a < b) == dir) { slist[i] = b; slist[l] = a; }
            __syncthreads();
        }
    }
    bool vld = false;
    float4 bx, ob; float ar, lb, sc;
    if (t < TOPK) {
        decode_one(n, slist[t], loc, reg, info, &bx, &ob, &ar, &lb, &sc, &vld);
    } else {
        bx = make_float4(0, 0, 0, 0); ob = bx; ar = 0; lb = 0; sc = 0;
    }
    *(float4*)&g_box[n][t][0] = bx;
    *(float4*)&g_obox[n][t][0] = ob;
    g_area[n][t] = ar; g_lab[n][t] = lb; g_sc[n][t] = sc;
    uint bal = __ballot_sync(0xffffffffu, vld);
    if ((t & 31) == 0) g_validbits[n][t >> 5] = bal;
}

// ---------------- K4: finish (hist-select + rank-sort fast path) -------------
__global__ __launch_bounds__(1024, 1) void k_finish(const float* __restrict__ cls,
                                                    const float* __restrict__ ctr,
                                                    const float* __restrict__ loc,
                                                    const float* __restrict__ reg,
                                                    const float* __restrict__ info,
                                                    float* __restrict__ out) {
    extern __shared__ uint smaskd[];                 // 128 KB (slow-path mask)
    __shared__ ull slist[CAP2];                      // 16 KB; fast path reuses:
                                                     //  as uint[4096] hist, then
                                                     //  [0,SRT) keys, [SRT,2*SRT) sorted
    __shared__ uint shist[256];
    __shared__ uint smisc[8];
    __shared__ float4 sbox[SEL], sob[SEL];
    __shared__ float sar[SEL], slb[SEL], ssc[SEL];
    __shared__ uint svalid[8];
    __shared__ uint smask[SEL * 8];                  // 8 KB
    __shared__ int s_path;                           // 0 fast-ok, 1 rebuild, 2 full-nms
    __shared__ float4 sobF[KPAD];
    __shared__ float sarF[KPAD], slbF[KPAD];
    int n = blockIdx.x;
    int t = threadIdx.x;
    int lane = t & 31;
    uint* h4k = (uint*)slist;                        // 4096-bin exact hist
    if (t < 600) out[(size_t)n * 600 + t] = 0.0f;
    for (int q = t; q < 4096; q += 1024) g_hist14[n][q] = 0u;   // reset for next call
    for (int q = t; q < 4096; q += 1024) h4k[q] = 0u;
    uint attempted = g_candcnt[n];
    uint M = attempted > CAP ? CAP : attempted;
    if (t == 0) { smisc[3] = 0u; s_path = 0; }
    __syncthreads();
    // fused: completeness count + exact 4096-bin hist of key high bits >> 18
    {
        uint Vb = g_T[n] << 18;
        uint local = 0;
        for (uint idx = t; idx < M; idx += 1024) {
            uint bits = (uint)(g_cand[n][idx] >> 32);
            if (bits >= Vb) local++;
            uint b = bits >> 18;
            if (b > 4095u) b = 4095u;
            atomicAdd(&h4k[b], 1u);
        }
        if (local) atomicAdd(&smisc[3], local);
    }
    __syncthreads();
    if (smisc[3] < TOPK || attempted > CAP) {
        if (t == 0) s_path = 1;
    }
    __syncthreads();
    if (s_path == 0) {
        // ---- pick finest bin threshold with suffix count in [SEL, SRT] ----
        uint loc16[16]; uint s = 0;
        if (t < 256) {
#pragma unroll
            for (int i = 0; i < 16; i++) { loc16[i] = h4k[t * 16 + i]; s += loc16[i]; }
            shist[t] = s;
        }
        __syncthreads();
        for (int off = 1; off < 256; off <<= 1) {    // suffix scan of chunk sums
            uint v = 0;
            if (t < 256 && t + off < 256) v = shist[t + off];
            __syncthreads();
            if (t < 256) shist[t] += v;
            __syncthreads();
        }
        if (t < 256) {
            uint mine = shist[t];
            uint above = (t < 255) ? shist[t + 1] : 0u;
            if (mine >= SEL && above < SEL) {        // unique crossing chunk
                uint cum = above;
                for (int i = 15; i >= 0; i--) {
                    cum += loc16[i];
                    if (cum >= SEL) {                // largest bin w/ cnt >= SEL
                        smisc[0] = ((uint)(t * 16 + i)) << 18;   // sstar
                        smisc[4] = cum;              // W = selected count
                        break;
                    }
                }
            }
        }
        __syncthreads();
        if (smisc[4] > SRT) {                        // boundary bin too fat
            if (t == 0) s_path = 2;
        }
        __syncthreads();
        if (s_path == 0) {
            uint sstar = smisc[0];
            if (t == 0) smisc[2] = 0u;
            if (t < 2 * SRT) slist[t] = 0ull;        // keys + sorted regions
            __syncthreads();
            for (uint idx = t; idx < M; idx += 1024) {
                ull key = g_cand[n][idx];
                if ((uint)(key >> 32) >= sstar) {
                    uint pos = atomicAdd(&smisc[2], 1u);
                    if (pos < SRT) slist[pos] = key;
                }
            }
            __syncthreads();
            uint W = smisc[2];                       // == smisc[4] <= SRT
            // ---- rank-by-counting sort (keys unique; no barriers) ----
            if (t < (int)W) {
                ull kt = slist[t];
                uint rank = 0;
#pragma unroll 4
                for (uint j = 0; j < W; j++) {
                    ull kj = slist[j];
                    rank += (kj > kt) ? 1u : 0u;
                }
                slist[SRT + rank] = kt;              // sorted desc
            }
            __syncthreads();
            if (t < SEL) {
                bool vld;
                decode_one(n, slist[SRT + t], loc, reg, info,
                           &sbox[t], &sob[t], &sar[t], &slb[t], &ssc[t], &vld);
                uint bal = __ballot_sync(0xffffffffu, vld);
                if ((t & 31) == 0) svalid[t >> 5] = bal;
            }
            __syncthreads();
            {
                int warp = t >> 5;
#pragma unroll
                for (int r = 0; r < 8; r++) {
                    int i = warp * 8 + r;
                    float4 bi = sob[i];
                    float ai = sar[i];
                    float li = slb[i];
#pragma unroll
                    for (int wd = 0; wd < 8; wd++) {
                        int j = wd * 32 + lane;
                        bool sup = false;
                        if (j > i && slb[j] == li)
                            sup = iou_sup(bi, ai, sob[j], sar[j]);
                        uint bits = __ballot_sync(0xffffffffu, sup);
                        if (lane == 0) smask[i * 8 + wd] = bits;
                    }
                }
            }
            __syncthreads();
            if (t < 32) {
                uint validw = (lane < 8) ? svalid[lane] : 0u;
                uint removew = 0u;
                for (int g = 0; g < 8; g++) {
                    uint cur_sup = __shfl_sync(0xffffffffu, removew, g);
                    uint cur_val = __shfl_sync(0xffffffffu, validw, g);
                    uint rowv[32], diag[32];
#pragma unroll
                    for (int b = 0; b < 32; b++) {
                        rowv[b] = (lane < 8) ? smask[(g * 32 + b) * 8 + lane] : 0u;
                        diag[b] = smask[(g * 32 + b) * 8 + g];
                    }
#pragma unroll
                    for (int b = 0; b < 32; b++) {
                        bool alive = ((cur_val >> b) & 1u) && !((cur_sup >> b) & 1u);
                        if (alive) { removew |= rowv[b]; cur_sup |= diag[b]; }
                    }
                }
                uint keepw = validw & ~removew;
                int kv = __popc(keepw);
                int tot = kv;
#pragma unroll
                for (int o = 1; o < 32; o <<= 1)     // full-warp: uniform tot
                    tot += __shfl_xor_sync(0xffffffffu, tot, o);
                if (tot >= 100) {
                    int inc = kv;
                    for (int o = 1; o < 32; o <<= 1) {
                        int v = __shfl_up_sync(0xffffffffu, inc, o);
                        if (lane >= o) inc += v;
                    }
                    int basei = inc - kv;
                    uint m = keepw;
                    while (m) {
                        int b = __ffs(m) - 1;
                        m &= m - 1;
                        int rank = basei + __popc(keepw & ((1u << b) - 1u));
                        if (rank < 100) {
                            int i = lane * 32 + b;
                            float* o6 = out + ((size_t)n * 100 + rank) * 6;
                            float4 bx = sbox[i];
                            o6[0] = bx.x; o6[1] = bx.y; o6[2] = bx.z; o6[3] = bx.w;
                            o6[4] = slb[i]; o6[5] = ssc[i];
                        }
                    }
                } else if (lane == 0) {
                    s_path = 2;                      // need full-width NMS
                }
            }
            __syncthreads();
        }
    }
    if (s_path == 0) {
        if (t == 0) g_candcnt[n] = 0u;
        return;                                      // fast path done
    }
    // ================= slow path (guarded; never in practice) =================
    if (s_path == 1) {                               // exact candidate rebuild
        if (t < 256) shist[t] = 0u;
        if (t == 0) g_candcnt[n] = 0u;
        __syncthreads();
        const float* clsn = cls + (size_t)n * CPE;
        const float* ctrn = ctr + (size_t)n * PP;
        for (int j = t; j < CPE; j += 1024) {
            int p = j % PP;
            float s = sig_exact(clsn[j]);
            if (s > 0.05f) {
                uint b = __float_as_uint(__fmul_rn(s, sig_exact(ctrn[p]))) >> 24;
                if (b) atomicAdd(&shist[b], 1u);
            }
        }
        __syncthreads();
        if (t == 0) {
            uint cum = 0, b1 = 1;
            for (int b = 255; b >= 1; b--) {
                cum += shist[b];
                if (cum >= TOPK) { b1 = (uint)b; break; }
            }
            smisc[4] = b1;
        }
        __syncthreads();
        uint b1 = smisc[4];
        for (int j = t; j < CPE; j += 1024) {
            int p = j % PP;
            float s = sig_exact(clsn[j]);
            if (s > 0.05f) {
                float score = __fmul_rn(s, sig_exact(ctrn[p]));
                uint sb = __float_as_uint(score);
                if ((sb >> 24) >= b1) {
                    int c = j / PP;
                    uint i = (uint)(p * NCLS + c);
                    ull key = ((ull)sb << 32) | (ull)(0xFFFFFFFFu - i);
                    uint pos = atomicAdd(&g_candcnt[n], 1u);
                    if (pos < CAP) g_cand[n][pos] = key;
                }
            }
        }
        __syncthreads();
        attempted = g_candcnt[n];
        M = attempted > CAP ? CAP : attempted;
    }
    refine_core(n, M, loc, reg, info, slist, shist, smisc);
    __syncthreads();
    if (t < 600) out[(size_t)n * 600 + t] = 0.0f;    // re-zero (fast may have run)
    sobF[t] = *(float4*)&g_obox[n][t][0];
    sarF[t] = g_area[n][t];
    slbF[t] = g_lab[n][t];
    __syncthreads();
    int warp = t >> 5;
    for (int r = 0; r < 32; r++) {
        int i = r * 32 + warp;
        float4 bi = sobF[i];
        float ai = sarF[i];
        float li = slbF[i];
        uint myword = 0u;
        for (int w = r; w < 32; w++) {
            int j = w * 32 + lane;
            bool sup = false;
            if (j > i && slbF[j] == li)
                sup = iou_sup(bi, ai, sobF[j], sarF[j]);
            uint bits = __ballot_sync(0xffffffffu, sup);
            if (lane == w) myword = bits;
        }
        smaskd[i * 32 + lane] = (lane >= r) ? myword : 0u;
    }
    __syncthreads();
    if (t < 32) {
        uint validw = g_validbits[n][lane];
        uint removew = 0u;
        for (int g = 0; g < 32; g++) {
            uint cur_sup = __shfl_sync(0xffffffffu, removew, g);
            uint cur_val = __shfl_sync(0xffffffffu, validw, g);
            uint rowv[32], diag[32];
#pragma unroll
            for (int b = 0; b < 32; b++) {
                rowv[b] = smaskd[(g * 32 + b) * 32 + lane];
                diag[b] = smaskd[(g * 32 + b) * 32 + g];
            }
#pragma unroll
            for (int b = 0; b < 32; b++) {
                bool alive = ((cur_val >> b) & 1u) && !((cur_sup >> b) & 1u);
                if (alive) { removew |= rowv[b]; cur_sup |= diag[b]; }
            }
        }
        uint keepw = validw & ~removew;
        int cnt = __popc(keepw);
        int inc = cnt;
        for (int o = 1; o < 32; o <<= 1) {
            int v = __shfl_up_sync(0xffffffffu, inc, o);
            if (lane >= o) inc += v;
        }
        int basei = inc - cnt;
        uint m = keepw;
        while (m) {
            int b = __ffs(m) - 1;
            m &= m - 1;
            int rank = basei + __popc(keepw & ((1u << b) - 1u));
            if (rank < 100) {
                int i = lane * 32 + b;
                float* o6 = out + ((size_t)n * 100 + rank) * 6;
                o6[0] = g_box[n][i][0]; o6[1] = g_box[n][i][1];
                o6[2] = g_box[n][i][2]; o6[3] = g_box[n][i][3];
                o6[4] = g_lab[n][i];    o6[5] = g_sc[n][i];
            }
        }
    }
    __syncthreads();
    if (t == 0) g_candcnt[n] = 0u;
}

// ---------------- launch -----------------------------------------------------
extern "C" void kernel_launch(void* const* d_in, const int* in_sizes, int n_in,
                              void* d_out, int out_size) {
    const float* loc  = (const float*)d_in[0];
    const float* cls  = (const float*)d_in[1];
    const float* reg  = (const float*)d_in[2];
    const float* ctr  = (const float*)d_in[3];
    const float* info = (const float*)d_in[4];
    float* out = (float*)d_out;
    (void)in_sizes; (void)n_in; (void)out_size;

    cudaFuncSetAttribute(k_finish, cudaFuncAttributeMaxDynamicSharedMemorySize,
                         KPAD * 32 * 4);

    k_hist<<<dim3(SBLK, NIMG), 256>>>(cls, ctr);
    k_prep<<<dim3(60, NIMG), 256>>>(ctr);
    k_compact<<<dim3(15, 20, NIMG), 256>>>(cls, ctr);
    k_finish<<<NIMG, 1024, KPAD * 32 * 4>>>(cls, ctr, loc, reg, info, out);
}

// round 14
// speedup vs baseline: 1.2709x; 1.0842x over previous
#include <cuda_runtime.h>
#include <math.h>
#include <stdint.h>

// FCOS post-process, GB300 (sm_103a), round 14.
// = round 13 with the fast-path NMS window shrunk 256->192 and the mask
//   phase restricted to upper-triangle words (lower-triangle words are
//   identically zero). Slow path unchanged (R11-proven).

#define NIMG 8
#define NCLS 80
#define PP   15200
#define CPE  (NCLS*PP)        // 1216000
#define TOPK 1000
#define KPAD 1024
#define SEL  192              // early-stop NMS window (6 words of 32)
#define NW   6                // SEL/32
#define SRT  512              // selection width cap (SEL + tie slack)
#define CAP  262144
#define CAP2 2048
#define NSAMP 960
#define NITEM (NSAMP*10)
#define SBLK 38
#define TARGET_S 100
#define C0 (-2.9444389791664403f)   // logit(0.05)
typedef unsigned long long ull;
typedef unsigned int uint;

// ---------------- device scratch (module-load zeroed; self-cleaning) ---------
__device__ ull  g_cand[NIMG][CAP];                   // 16 MB
__device__ uint g_hist14[NIMG][4096];
__device__ uint g_candcnt[NIMG];
__device__ uint g_T[NIMG];
__device__ float g_xmin[NIMG][PP];
__device__ float g_box [NIMG][KPAD][4];
__device__ float g_obox[NIMG][KPAD][4];
__device__ float g_area[NIMG][KPAD];
__device__ float g_lab [NIMG][KPAD];
__device__ float g_sc  [NIMG][KPAD];
__device__ uint g_validbits[NIMG][32];

__device__ __forceinline__ float sig_exact(float v) {
    return 1.0f / (1.0f + expf(-v));
}
__device__ __forceinline__ float score_apx(float x, float eyp) {
    return __frcp_rn(__fmul_rn(__fadd_rn(1.0f, __expf(-x)), eyp));
}
__device__ __forceinline__ float4 f4max(float4 a, float4 b) {
    return make_float4(fmaxf(a.x, b.x), fmaxf(a.y, b.y),
                      fmaxf(a.z, b.z), fmaxf(a.w, b.w));
}

// R11 radix-select (slow path only). smisc[0] = exact threshold for `rank`.
__device__ void radix_select(int n, uint M, uint rank, uint* shist, uint* smisc) {
    int t = threadIdx.x;
    int bdim = blockDim.x;
    if (t == 0) { smisc[0] = 0u; smisc[1] = rank; }
    __syncthreads();
    for (int lvl = 3; lvl >= 0; lvl--) {
        if (t < 256) shist[t] = 0u;
        __syncthreads();
        uint pfx = smisc[0];
        for (uint idx = t; idx < M; idx += bdim) {
            uint bits = (uint)(g_cand[n][idx] >> 32);
            bool cond = (lvl == 3) || ((bits >> ((lvl + 1) * 8)) == pfx);
            if (cond) atomicAdd(&shist[(bits >> (lvl * 8)) & 255u], 1u);
        }
        __syncthreads();
        for (int off = 1; off < 256; off <<= 1) {
            uint v = 0;
            if (t < 256 && t + off < 256) v = shist[t + off];
            __syncthreads();
            if (t < 256) shist[t] += v;
            __syncthreads();
        }
        if (t < 256) {
            uint rr = smisc[1];
            uint mine = shist[t];
            uint above = (t < 255) ? shist[t + 1] : 0u;
            if (mine >= rr && above < rr) {
                smisc[1] = rr - above;
                smisc[0] = (smisc[0] << 8) | (uint)t;
            }
        }
        __syncthreads();
    }
}

// ---------------- K1: sampled hist via SMEM, sparse merge --------------------
__global__ __launch_bounds__(256) void k_hist(const float* __restrict__ cls,
                                              const float* __restrict__ ctr) {
    __shared__ uint sh[4096];
    int n = blockIdx.y;
    int t = threadIdx.x;
    for (int q = t; q < 4096; q += 256) sh[q] = 0u;
    __syncthreads();
    int item = blockIdx.x * 256 + t;
    if (item < NITEM) {
        int k  = item % NSAMP;
        int cb = item / NSAMP;
        int p = (k >> 4) * 253 + (k & 15);           // 60 runs of 16 points
        float eyp = __fadd_rn(1.0f, __expf(-ctr[(size_t)n * PP + p]));
        const float* base = cls + (size_t)n * CPE + p + (size_t)cb * 8 * PP;
        float xs[8];
#pragma unroll
        for (int i = 0; i < 8; i++) xs[i] = base[(size_t)i * PP];
#pragma unroll
        for (int i = 0; i < 8; i++) {
            if (xs[i] > C0) {
                uint b14 = __float_as_uint(score_apx(xs[i], eyp)) >> 18;
                if (b14 > 4095u) b14 = 4095u;
                if (b14) atomicAdd(&sh[b14], 1u);
            }
        }
    }
    __syncthreads();
    for (int q = t; q < 4096; q += 256) {
        uint v = sh[q];
        if (v) atomicAdd(&g_hist14[n][q], v);        // sparse: few hundred/block
    }
}

// ---------------- K2: per-block t14 + xmin slice (grid 60 x NIMG) ------------
__global__ __launch_bounds__(256) void k_prep(const float* __restrict__ ctr) {
    __shared__ uint ss[256];
    __shared__ float s_edge;
    int n = blockIdx.y;
    int t = threadIdx.x;
    uint loc[16]; uint s = 0;
#pragma unroll
    for (int i = 0; i < 16; i++) { loc[i] = g_hist14[n][t * 16 + i]; s += loc[i]; }
    ss[t] = s;
    __syncthreads();
    for (int off = 1; off < 256; off <<= 1) {        // suffix scan
        uint v = (t + off < 256) ? ss[t + off] : 0u;
        __syncthreads();
        ss[t] += v;
        __syncthreads();
    }
    uint mine = ss[t];
    uint above = (t + 1 < 256) ? ss[t + 1] : 0u;
    if (mine >= TARGET_S && above < TARGET_S) {      // unique crossing chunk
        uint cum = above, T = 1;
        for (int i = 15; i >= 0; i--) {
            cum += loc[i];
            if (cum >= TARGET_S) { T = (uint)(t * 16 + i); break; }
        }
        if (T < 1) T = 1;
        uint gate = (T > 2) ? T - 1 : 1u;
        g_T[n] = T;                                  // identical across blocks
        s_edge = __uint_as_float(gate << 18);
    }
    if (t == 0 && ss[0] < TARGET_S) {                // degenerate: keep all
        g_T[n] = 1;
        s_edge = __uint_as_float(1u << 18);
    }
    __syncthreads();
    float edge = s_edge;
    int p = blockIdx.x * 256 + t;
    if (p < PP) {
        float eyp = __fadd_rn(1.0f, __expf(-ctr[(size_t)n * PP + p]));
        float K = __fdividef(1.0f, __fmul_rn(edge, eyp)) - 1.0f;
        float xm = (K > 0.0f) ? (-__logf(K) - 0.002f) : 3.0e38f;
        g_xmin[n][p] = fmaxf(xm, C0);
    }
}

// ---------------- K3: max-gated full scan, 4 classes/thread ------------------
__global__ __launch_bounds__(256) void k_compact(const float* __restrict__ cls,
                                                 const float* __restrict__ ctr) {
    int n = blockIdx.z;
    int q = blockIdx.x * 256 + threadIdx.x;
    if (q >= PP / 4) return;
    int pb = q * 4;
    float4 xm4 = *(const float4*)&g_xmin[n][pb];
    float xm[4] = {xm4.x, xm4.y, xm4.z, xm4.w};
    int c0 = blockIdx.y * 4;
    const float* base = cls + (size_t)n * CPE + pb;
    float4 xv[4];
#pragma unroll
    for (int i = 0; i < 4; i++)
        xv[i] = *(const float4*)(base + (size_t)(c0 + i) * PP);
    float4 m4 = f4max(f4max(xv[0], xv[1]), f4max(xv[2], xv[3]));
    float mj[4] = {m4.x, m4.y, m4.z, m4.w};
#pragma unroll
    for (int j = 0; j < 4; j++) {
        if (mj[j] >= xm[j]) {                        // rare: some class passes
#pragma unroll
            for (int i = 0; i < 4; i++) {
                float x = (j == 0) ? xv[i].x : (j == 1) ? xv[i].y
                        : (j == 2) ? xv[i].z : xv[i].w;
                if (x >= xm[j]) {
                    float s = sig_exact(x);
                    if (s > 0.05f) {                 // exact candidacy
                        float y = ctr[(size_t)n * PP + pb + j];
                        float score = __fmul_rn(s, sig_exact(y));
                        uint sb = __float_as_uint(score);
                        uint idx = (uint)((pb + j) * NCLS + (c0 + i));
                        ull key = ((ull)sb << 32) | (ull)(0xFFFFFFFFu - idx);
                        uint pos = atomicAdd(&g_candcnt[n], 1u);
                        if (pos < CAP) g_cand[n][pos] = key;
                    }
                }
            }
        }
    }
}

// ---------------- decode helper ----------------------------------------------
__device__ __forceinline__ void decode_one(int n, ull key,
        const float* loc, const float* reg, const float* info,
        float4* box4, float4* ob4, float* area, float* lab, float* sc, bool* valid) {
    float x1 = 0, y1 = 0, x2 = 0, y2 = 0, labf = 0, score = 0;
    float ox1 = 0, oy1 = 0, ox2 = 0, oy2 = 0, ar = 0;
    bool vld = false;
    uint sb = (uint)(key >> 32);
    if (sb) {
        score = __uint_as_float(sb);
        uint i = 0xFFFFFFFFu - (uint)(key & 0xFFFFFFFFull);
        int p = (int)(i / NCLS);
        int c = (int)(i - (uint)(p * NCLS));
        labf = (float)(c + 1);
        float lx = loc[2 * p], ly = loc[2 * p + 1];
        float rl = reg[((size_t)(n * 4 + 0)) * PP + p];
        float rt = reg[((size_t)(n * 4 + 1)) * PP + p];
        float rr = reg[((size_t)(n * 4 + 2)) * PP + p];
        float rb = reg[((size_t)(n * 4 + 3)) * PP + p];
        float hm1 = __fsub_rn(info[2 * n + 0], 1.0f);
        float wm1 = __fsub_rn(info[2 * n + 1], 1.0f);
        x1 = fminf(fmaxf(__fsub_rn(lx, rl), 0.0f), wm1);
        y1 = fminf(fmaxf(__fsub_rn(ly, rt), 0.0f), hm1);
        x2 = fminf(fmaxf(__fadd_rn(lx, rr), 0.0f), wm1);
        y2 = fminf(fmaxf(__fadd_rn(ly, rb), 0.0f), hm1);
        vld = (score > 0.0f) &&
              (__fsub_rn(x2, x1) >= 0.0f) && (__fsub_rn(y2, y1) >= 0.0f);
        float off = __fmul_rn(labf, 1.0e5f);
        ox1 = __fadd_rn(x1, off); oy1 = __fadd_rn(y1, off);
        ox2 = __fadd_rn(x2, off); oy2 = __fadd_rn(y2, off);
        ar = __fmul_rn(fmaxf(__fsub_rn(ox2, ox1), 0.0f),
                       fmaxf(__fsub_rn(oy2, oy1), 0.0f));
    }
    *box4 = make_float4(x1, y1, x2, y2);
    *ob4  = make_float4(ox1, oy1, ox2, oy2);
    *area = ar; *lab = labf; *sc = score; *valid = vld;
}

__device__ __forceinline__ bool iou_sup(float4 bi, float ai, float4 bj, float aj) {
    float wv = fmaxf(__fsub_rn(fminf(bi.z, bj.z), fmaxf(bi.x, bj.x)), 0.0f);
    float hv = fmaxf(__fsub_rn(fminf(bi.w, bj.w), fmaxf(bi.y, bj.y)), 0.0f);
    float inter = __fmul_rn(wv, hv);
    float denom = __fadd_rn(__fsub_rn(__fadd_rn(ai, aj), inter), 1e-9f);
    return inter > __fmul_rn(0.6f, denom);           // iou > 0.6
}

// ---------------- full refine (slow path only; R11 proven) -------------------
__device__ void refine_core(int n, uint M,
                            const float* __restrict__ loc,
                            const float* __restrict__ reg,
                            const float* __restrict__ info,
                            ull* slist, uint* shist, uint* smisc) {
    int t = threadIdx.x;
    if (M <= CAP2) {
        for (int q = t; q < CAP2; q += 1024)
            slist[q] = (q < (int)M) ? g_cand[n][q] : 0ull;
        __syncthreads();
    } else {
        radix_select(n, M, TOPK, shist, smisc);
        uint sstar = smisc[0];
        if (t == 0) smisc[2] = 0u;
        for (int q = t; q < CAP2; q += 1024) slist[q] = 0ull;
        __syncthreads();
        for (uint idx = t; idx < M; idx += 1024) {
            ull key = g_cand[n][idx];
            if ((uint)(key >> 32) >= sstar) {
                uint pos = atomicAdd(&smisc[2], 1u);
                if (pos < CAP2) slist[pos] = key;
            }
        }
        __syncthreads();
    }
    for (int k2 = 2; k2 <= CAP2; k2 <<= 1) {
        for (int s2 = k2 >> 1; s2 >= 1; s2 >>= 1) {
            int i = ((t & ~(s2 - 1)) << 1) | (t & (s2 - 1));
            int l = i | s2;
            ull a = slist[i], b = slist[l];
            bool dir = ((i & k2) == 0);
            if ((a < b) == dir) { slist[i] = b; slist[l] = a; }
            __syncthreads();
        }
    }
    bool vld = false;
    float4 bx, ob; float ar, lb, sc;
    if (t < TOPK) {
        decode_one(n, slist[t], loc, reg, info, &bx, &ob, &ar, &lb, &sc, &vld);
    } else {
        bx = make_float4(0, 0, 0, 0); ob = bx; ar = 0; lb = 0; sc = 0;
    }
    *(float4*)&g_box[n][t][0] = bx;
    *(float4*)&g_obox[n][t][0] = ob;
    g_area[n][t] = ar; g_lab[n][t] = lb; g_sc[n][t] = sc;
    uint bal = __ballot_sync(0xffffffffu, vld);
    if ((t & 31) == 0) g_validbits[n][t >> 5] = bal;
}

// ---------------- K4: finish (hist-select + rank-sort + 192-NMS) -------------
__global__ __launch_bounds__(1024, 1) void k_finish(const float* __restrict__ cls,
                                                    const float* __restrict__ ctr,
                                                    const float* __restrict__ loc,
                                                    const float* __restrict__ reg,
                                                    const float* __restrict__ info,
                                                    float* __restrict__ out) {
    extern __shared__ uint smaskd[];                 // 128 KB (slow-path mask)
    __shared__ ull slist[CAP2];                      // 16 KB; fast path reuses:
                                                     //  uint[4096] hist, then
                                                     //  [0,SRT) keys, [SRT,2SRT) sorted
    __shared__ uint shist[256];
    __shared__ uint smisc[8];
    __shared__ float4 sbox[SEL], sob[SEL];
    __shared__ float sar[SEL], slb[SEL], ssc[SEL];
    __shared__ uint svalid[NW];
    __shared__ uint smask[SEL * NW];                 // 4.5 KB
    __shared__ int s_path;                           // 0 fast-ok, 1 rebuild, 2 full-nms
    __shared__ float4 sobF[KPAD];
    __shared__ float sarF[KPAD], slbF[KPAD];
    int n = blockIdx.x;
    int t = threadIdx.x;
    int lane = t & 31;
    uint* h4k = (uint*)slist;                        // 4096-bin exact hist
    if (t < 600) out[(size_t)n * 600 + t] = 0.0f;
    for (int q = t; q < 4096; q += 1024) g_hist14[n][q] = 0u;   // reset for next call
    for (int q = t; q < 4096; q += 1024) h4k[q] = 0u;
    uint attempted = g_candcnt[n];
    uint M = attempted > CAP ? CAP : attempted;
    if (t == 0) { smisc[3] = 0u; s_path = 0; }
    __syncthreads();
    // fused: completeness count + exact 4096-bin hist of key high bits >> 18
    {
        uint Vb = g_T[n] << 18;
        uint local = 0;
        for (uint idx = t; idx < M; idx += 1024) {
            uint bits = (uint)(g_cand[n][idx] >> 32);
            if (bits >= Vb) local++;
            uint b = bits >> 18;
            if (b > 4095u) b = 4095u;
            atomicAdd(&h4k[b], 1u);
        }
        if (local) atomicAdd(&smisc[3], local);
    }
    __syncthreads();
    if (smisc[3] < TOPK || attempted > CAP) {
        if (t == 0) s_path = 1;
    }
    __syncthreads();
    if (s_path == 0) {
        // ---- pick finest bin threshold with suffix count in [SEL, SRT] ----
        uint loc16[16]; uint s = 0;
        if (t < 256) {
#pragma unroll
            for (int i = 0; i < 16; i++) { loc16[i] = h4k[t * 16 + i]; s += loc16[i]; }
            shist[t] = s;
        }
        __syncthreads();
        for (int off = 1; off < 256; off <<= 1) {    // suffix scan of chunk sums
            uint v = 0;
            if (t < 256 && t + off < 256) v = shist[t + off];
            __syncthreads();
            if (t < 256) shist[t] += v;
            __syncthreads();
        }
        if (t < 256) {
            uint mine = shist[t];
            uint above = (t < 255) ? shist[t + 1] : 0u;
            if (mine >= SEL && above < SEL) {        // unique crossing chunk
                uint cum = above;
                for (int i = 15; i >= 0; i--) {
                    cum += loc16[i];
                    if (cum >= SEL) {                // largest bin w/ cnt >= SEL
                        smisc[0] = ((uint)(t * 16 + i)) << 18;   // sstar
                        smisc[4] = cum;              // W = selected count
                        break;
                    }
                }
            }
        }
        __syncthreads();
        if (smisc[4] > SRT) {                        // boundary bin too fat
            if (t == 0) s_path = 2;
        }
        __syncthreads();
        if (s_path == 0) {
            uint sstar = smisc[0];
            if (t == 0) smisc[2] = 0u;
            if (t < 2 * SRT) slist[t] = 0ull;        // keys + sorted regions
            __syncthreads();
            for (uint idx = t; idx < M; idx += 1024) {
                ull key = g_cand[n][idx];
                if ((uint)(key >> 32) >= sstar) {
                    uint pos = atomicAdd(&smisc[2], 1u);
                    if (pos < SRT) slist[pos] = key;
                }
            }
            __syncthreads();
            uint W = smisc[2];                       // == smisc[4] <= SRT
            // ---- rank-by-counting sort (keys unique; no barriers) ----
            if (t < (int)W) {
                ull kt = slist[t];
                uint rank = 0;
#pragma unroll 4
                for (uint j = 0; j < W; j++) {
                    ull kj = slist[j];
                    rank += (kj > kt) ? 1u : 0u;
                }
                slist[SRT + rank] = kt;              // sorted desc
            }
            __syncthreads();
            if (t < SEL) {
                bool vld;
                decode_one(n, slist[SRT + t], loc, reg, info,
                           &sbox[t], &sob[t], &sar[t], &slb[t], &ssc[t], &vld);
                uint bal = __ballot_sync(0xffffffffu, vld);
                if ((t & 31) == 0) svalid[t >> 5] = bal;
            }
            __syncthreads();
            // mask SELxSEL: warp handles rows [warp*NW, warp*NW+NW);
            // only upper-triangle words computed (lower are identically 0).
            {
                int warp = t >> 5;
#pragma unroll
                for (int r = 0; r < NW; r++) {
                    int i = warp * NW + r;
                    int w0 = i >> 5;                 // warp-uniform
                    float4 bi = sob[i];
                    float ai = sar[i];
                    float li = slb[i];
                    if (lane == 0)
                        for (int wd = 0; wd < w0; wd++) smask[i * NW + wd] = 0u;
                    for (int wd = w0; wd < NW; wd++) {
                        int j = wd * 32 + lane;
                        bool sup = false;
                        if (j > i && slb[j] == li)
                            sup = iou_sup(bi, ai, sob[j], sar[j]);
                        uint bits = __ballot_sync(0xffffffffu, sup);
                        if (lane == 0) smask[i * NW + wd] = bits;
                    }
                }
            }
            __syncthreads();
            if (t < 32) {
                uint validw = (lane < NW) ? svalid[lane] : 0u;
                uint removew = 0u;
                for (int g = 0; g < NW; g++) {
                    uint cur_sup = __shfl_sync(0xffffffffu, removew, g);
                    uint cur_val = __shfl_sync(0xffffffffu, validw, g);
                    uint rowv[32], diag[32];
#pragma unroll
                    for (int b = 0; b < 32; b++) {
                        rowv[b] = (lane < NW) ? smask[(g * 32 + b) * NW + lane] : 0u;
                        diag[b] = smask[(g * 32 + b) * NW + g];
                    }
#pragma unroll
                    for (int b = 0; b < 32; b++) {
                        bool alive = ((cur_val >> b) & 1u) && !((cur_sup >> b) & 1u);
                        if (alive) { removew |= rowv[b]; cur_sup |= diag[b]; }
                    }
                }
                uint keepw = validw & ~removew;
                int kv = __popc(keepw);
                int tot = kv;
#pragma unroll
                for (int o = 1; o < 32; o <<= 1)     // full-warp: uniform tot
                    tot += __shfl_xor_sync(0xffffffffu, tot, o);
                if (tot >= 100) {
                    int inc = kv;
                    for (int o = 1; o < 32; o <<= 1) {
                        int v = __shfl_up_sync(0xffffffffu, inc, o);
                        if (lane >= o) inc += v;
                    }
                    int basei = inc - kv;
                    uint m = keepw;
                    while (m) {
                        int b = __ffs(m) - 1;
                        m &= m - 1;
                        int rank = basei + __popc(keepw & ((1u << b) - 1u));
                        if (rank < 100) {
                            int i = lane * 32 + b;
                            float* o6 = out + ((size_t)n * 100 + rank) * 6;
                            float4 bx = sbox[i];
                            o6[0] = bx.x; o6[1] = bx.y; o6[2] = bx.z; o6[3] = bx.w;
                            o6[4] = slb[i]; o6[5] = ssc[i];
                        }
                    }
                } else if (lane == 0) {
                    s_path = 2;                      // need full-width NMS
                }
            }
            __syncthreads();
        }
    }
    if (s_path == 0) {
        if (t == 0) g_candcnt[n] = 0u;
        return;                                      // fast path done
    }
    // ================= slow path (guarded; never in practice) =================
    if (s_path == 1) {                               // exact candidate rebuild
        if (t < 256) shist[t] = 0u;
        if (t == 0) g_candcnt[n] = 0u;
        __syncthreads();
        const float* clsn = cls + (size_t)n * CPE;
        const float* ctrn = ctr + (size_t)n * PP;
        for (int j = t; j < CPE; j += 1024) {
            int p = j % PP;
            float s = sig_exact(clsn[j]);
            if (s > 0.05f) {
                uint b = __float_as_uint(__fmul_rn(s, sig_exact(ctrn[p]))) >> 24;
                if (b) atomicAdd(&shist[b], 1u);
            }
        }
        __syncthreads();
        if (t == 0) {
            uint cum = 0, b1 = 1;
            for (int b = 255; b >= 1; b--) {
                cum += shist[b];
                if (cum >= TOPK) { b1 = (uint)b; break; }
            }
            smisc[4] = b1;
        }
        __syncthreads();
        uint b1 = smisc[4];
        for (int j = t; j < CPE; j += 1024) {
            int p = j % PP;
            float s = sig_exact(clsn[j]);
            if (s > 0.05f) {
                float score = __fmul_rn(s, sig_exact(ctrn[p]));
                uint sb = __float_as_uint(score);
                if ((sb >> 24) >= b1) {
                    int c = j / PP;
                    uint i = (uint)(p * NCLS + c);
                    ull key = ((ull)sb << 32) | (ull)(0xFFFFFFFFu - i);
                    uint pos = atomicAdd(&g_candcnt[n], 1u);
                    if (pos < CAP) g_cand[n][pos] = key;
                }
            }
        }
        __syncthreads();
        attempted = g_candcnt[n];
        M = attempted > CAP ? CAP : attempted;
    }
    refine_core(n, M, loc, reg, info, slist, shist, smisc);
    __syncthreads();
    if (t < 600) out[(size_t)n * 600 + t] = 0.0f;    // re-zero (fast may have run)
    sobF[t] = *(float4*)&g_obox[n][t][0];
    sarF[t] = g_area[n][t];
    slbF[t] = g_lab[n][t];
    __syncthreads();
    int warp = t >> 5;
    for (int r = 0; r < 32; r++) {
        int i = r * 32 + warp;
        float4 bi = sobF[i];
        float ai = sarF[i];
        float li = slbF[i];
        uint myword = 0u;
        for (int w = r; w < 32; w++) {
            int j = w * 32 + lane;
            bool sup = false;
            if (j > i && slbF[j] == li)
                sup = iou_sup(bi, ai, sobF[j], sarF[j]);
            uint bits = __ballot_sync(0xffffffffu, sup);
            if (lane == w) myword = bits;
        }
        smaskd[i * 32 + lane] = (lane >= r) ? myword : 0u;
    }
    __syncthreads();
    if (t < 32) {
        uint validw = g_validbits[n][lane];
        uint removew = 0u;
        for (int g = 0; g < 32; g++) {
            uint cur_sup = __shfl_sync(0xffffffffu, removew, g);
            uint cur_val = __shfl_sync(0xffffffffu, validw, g);
            uint rowv[32], diag[32];
#pragma unroll
            for (int b = 0; b < 32; b++) {
                rowv[b] = smaskd[(g * 32 + b) * 32 + lane];
                diag[b] = smaskd[(g * 32 + b) * 32 + g];
            }
#pragma unroll
            for (int b = 0; b < 32; b++) {
                bool alive = ((cur_val >> b) & 1u) && !((cur_sup >> b) & 1u);
                if (alive) { removew |= rowv[b]; cur_sup |= diag[b]; }
            }
        }
        uint keepw = validw & ~removew;
        int cnt = __popc(keepw);
        int inc = cnt;
        for (int o = 1; o < 32; o <<= 1) {
            int v = __shfl_up_sync(0xffffffffu, inc, o);
            if (lane >= o) inc += v;
        }
        int basei = inc - cnt;
        uint m = keepw;
        while (m) {
            int b = __ffs(m) - 1;
            m &= m - 1;
            int rank = basei + __popc(keepw & ((1u << b) - 1u));
            if (rank < 100) {
                int i = lane * 32 + b;
                float* o6 = out + ((size_t)n * 100 + rank) * 6;
                o6[0] = g_box[n][i][0]; o6[1] = g_box[n][i][1];
                o6[2] = g_box[n][i][2]; o6[3] = g_box[n][i][3];
                o6[4] = g_lab[n][i];    o6[5] = g_sc[n][i];
            }
        }
    }
    __syncthreads();
    if (t == 0) g_candcnt[n] = 0u;
}

// ---------------- launch -----------------------------------------------------
extern "C" void kernel_launch(void* const* d_in, const int* in_sizes, int n_in,
                              void* d_out, int out_size) {
    const float* loc  = (const float*)d_in[0];
    const float* cls  = (const float*)d_in[1];
    const float* reg  = (const float*)d_in[2];
    const float* ctr  = (const float*)d_in[3];
    const float* info = (const float*)d_in[4];
    float* out = (float*)d_out;
    (void)in_sizes; (void)n_in; (void)out_size;

    cudaFuncSetAttribute(k_finish, cudaFuncAttributeMaxDynamicSharedMemorySize,
                         KPAD * 32 * 4);

    k_hist<<<dim3(SBLK, NIMG), 256>>>(cls, ctr);
    k_prep<<<dim3(60, NIMG), 256>>>(ctr);
    k_compact<<<dim3(15, 20, NIMG), 256>>>(cls, ctr);
    k_finish<<<NIMG, 1024, KPAD * 32 * 4>>>(cls, ctr, loc, reg, info, out);
}